// round 1
// baseline (speedup 1.0000x reference)
#include <cuda_runtime.h>

// Problem constants (SidNetLayer): N=50000 nodes, E=600000 edges per signed
// adjacency, D=128 features, K=10 diffusion layers, restart C=0.15.
#define NMAX 50000
#define EMAX 600000
#define DD   128
#define DV   32          // D / 4 (float4 lanes per row)
#define KITER 10
#define CREST 0.15f

// ---------------- persistent device scratch (no allocation allowed) --------
__device__ int   g_cnt[2 * NMAX];        // histogram
__device__ int   g_cur[2 * NMAX];        // scatter cursors
__device__ int   g_start[2 * NMAX];      // exclusive row starts (p rows, then m rows offset by E)
__device__ int   g_bsum[256];            // block sums for scan
__device__ int   g_colp[EMAX];
__device__ float g_valp[EMAX];
__device__ int   g_colm[EMAX];
__device__ float g_valm[EMAX];
__device__ float g_P[2][(size_t)NMAX * DD];   // ping-pong dense buffers
__device__ float g_M[2][(size_t)NMAX * DD];

// ---------------- CSR build kernels ----------------------------------------
__global__ void zero_k(int n2) {
    int i = blockIdx.x * blockDim.x + threadIdx.x;
    if (i < n2) { g_cnt[i] = 0; g_cur[i] = 0; }
}

__global__ void hist_k(const int* __restrict__ rp, const int* __restrict__ rm,
                       int E, int n) {
    int i = blockIdx.x * blockDim.x + threadIdx.x;
    if (i < E) {
        atomicAdd(&g_cnt[rp[i]], 1);
        atomicAdd(&g_cnt[n + rm[i]], 1);
    }
}

// Exclusive scan of g_cnt[0..n2) into g_start, 1024 elements per block.
__global__ void scan1_k(int n2) {
    __shared__ int ws[32];
    int tid = threadIdx.x;
    int gid = blockIdx.x * 1024 + tid;
    int v = (gid < n2) ? g_cnt[gid] : 0;
    int x = v;
#pragma unroll
    for (int o = 1; o < 32; o <<= 1) {
        int y = __shfl_up_sync(0xffffffffu, x, o);
        if ((tid & 31) >= o) x += y;
    }
    if ((tid & 31) == 31) ws[tid >> 5] = x;
    __syncthreads();
    if (tid < 32) {
        int s = ws[tid];
        int t = s;
#pragma unroll
        for (int o = 1; o < 32; o <<= 1) {
            int y = __shfl_up_sync(0xffffffffu, t, o);
            if (tid >= o) t += y;
        }
        ws[tid] = t - s;                       // exclusive warp offset
        if (tid == 31) g_bsum[blockIdx.x] = t; // block total
    }
    __syncthreads();
    if (gid < n2) g_start[gid] = (x - v) + ws[tid >> 5];
}

__global__ void scan2_k(int nb) {
    if (threadIdx.x == 0 && blockIdx.x == 0) {
        int acc = 0;
        for (int i = 0; i < nb; i++) { int t = g_bsum[i]; g_bsum[i] = acc; acc += t; }
    }
}

__global__ void scan3_k(int n2) {
    int gid = blockIdx.x * blockDim.x + threadIdx.x;
    if (gid < n2) g_start[gid] += g_bsum[gid >> 10];
}

__global__ void scatter_k(const int* __restrict__ rp, const int* __restrict__ cp,
                          const float* __restrict__ vp,
                          const int* __restrict__ rm, const int* __restrict__ cm,
                          const float* __restrict__ vm, int E, int n) {
    int i = blockIdx.x * blockDim.x + threadIdx.x;
    if (i >= E) return;
    int r = rp[i];
    int pos = g_start[r] + atomicAdd(&g_cur[r], 1);
    g_colp[pos] = cp[i];
    g_valp[pos] = vp[i];
    r = rm[i];
    pos = (g_start[n + r] - E) + atomicAdd(&g_cur[n + r], 1);
    g_colm[pos] = cm[i];
    g_valm[pos] = vm[i];
}

// ---------------- fused diffusion iteration ---------------------------------
// One warp per output row. Accumulates both new_P[row] and new_M[row] in
// registers (float4 each). Edge cols/vals are loaded 32-wide once and
// broadcast by shuffle; dense gathers are warp-coalesced float4 (512B/row).
__global__ void __launch_bounds__(256)
diffuse_k(const float4* __restrict__ Ps, const float4* __restrict__ Ms,
          const float4* __restrict__ X4,
          float4* __restrict__ Pd, float4* __restrict__ Md,
          int n, int E) {
    int w = (blockIdx.x * blockDim.x + threadIdx.x) >> 5;
    int lane = threadIdx.x & 31;
    if (w >= n) return;

    float4 x = __ldg(&X4[(size_t)w * DV + lane]);
    float aP0 = CREST * x.x, aP1 = CREST * x.y, aP2 = CREST * x.z, aP3 = CREST * x.w;
    float aM0 = 0.f, aM1 = 0.f, aM2 = 0.f, aM3 = 0.f;

    // ---- positive edges: P[col] -> accP, M[col] -> accM
    {
        int s = g_start[w];
        int e = (w + 1 < n) ? g_start[w + 1] : E;
        for (int base = s; base < e; base += 32) {
            int idx = base + lane;
            int c = 0; float v = 0.f;
            if (idx < e) { c = g_colp[idx]; v = g_valp[idx]; }
            int cnt = min(32, e - base);
            for (int j = 0; j < cnt; j++) {
                int   cj = __shfl_sync(0xffffffffu, c, j);
                float vj = __shfl_sync(0xffffffffu, v, j);
                float4 p = __ldg(&Ps[(size_t)cj * DV + lane]);
                float4 q = __ldg(&Ms[(size_t)cj * DV + lane]);
                aP0 += vj * p.x; aP1 += vj * p.y; aP2 += vj * p.z; aP3 += vj * p.w;
                aM0 += vj * q.x; aM1 += vj * q.y; aM2 += vj * q.z; aM3 += vj * q.w;
            }
        }
    }
    // ---- negative edges: M[col] -> accP, P[col] -> accM
    {
        int s = g_start[n + w] - E;
        int e = (w + 1 < n) ? (g_start[n + w + 1] - E) : E;
        for (int base = s; base < e; base += 32) {
            int idx = base + lane;
            int c = 0; float v = 0.f;
            if (idx < e) { c = g_colm[idx]; v = g_valm[idx]; }
            int cnt = min(32, e - base);
            for (int j = 0; j < cnt; j++) {
                int   cj = __shfl_sync(0xffffffffu, c, j);
                float vj = __shfl_sync(0xffffffffu, v, j);
                float4 p = __ldg(&Ps[(size_t)cj * DV + lane]);
                float4 q = __ldg(&Ms[(size_t)cj * DV + lane]);
                aP0 += vj * q.x; aP1 += vj * q.y; aP2 += vj * q.z; aP3 += vj * q.w;
                aM0 += vj * p.x; aM1 += vj * p.y; aM2 += vj * p.z; aM3 += vj * p.w;
            }
        }
    }

    Pd[(size_t)w * DV + lane] = make_float4(aP0, aP1, aP2, aP3);
    Md[(size_t)w * DV + lane] = make_float4(aM0, aM1, aM2, aM3);
}

// ---------------- launch --------------------------------------------------
extern "C" void kernel_launch(void* const* d_in, const int* in_sizes, int n_in,
                              void* d_out, int out_size) {
    const int*   rp = (const int*)d_in[0];
    const int*   cp = (const int*)d_in[1];
    const float* vp = (const float*)d_in[2];
    const int*   rm = (const int*)d_in[3];
    const int*   cm = (const int*)d_in[4];
    const float* vm = (const float*)d_in[5];
    const float* X  = (const float*)d_in[6];
    const float* M0 = (const float*)d_in[7];

    int E = in_sizes[0];
    int n = in_sizes[6] / DD;
    int n2 = 2 * n;

    // CSR build (runs every launch; deterministic up to intra-row order)
    zero_k<<<(n2 + 255) / 256, 256>>>(n2);
    hist_k<<<(E + 255) / 256, 256>>>(rp, rm, E, n);
    int nb = (n2 + 1023) / 1024;
    scan1_k<<<nb, 1024>>>(n2);
    scan2_k<<<1, 32>>>(nb);
    scan3_k<<<(n2 + 255) / 256, 256>>>(n2);
    scatter_k<<<(E + 255) / 256, 256>>>(rp, cp, vp, rm, cm, vm, E, n);

    // ping-pong buffers
    float *gP = nullptr, *gM = nullptr;
    cudaGetSymbolAddress((void**)&gP, g_P);
    cudaGetSymbolAddress((void**)&gM, g_M);

    const float* Ps = X;
    const float* Ms = M0;
    int warps_per_block = 256 / 32;
    int grid = (n + warps_per_block - 1) / warps_per_block;

    for (int it = 0; it < KITER; ++it) {
        float *Pd, *Md;
        if (it == KITER - 1) {
            Pd = (float*)d_out;
            Md = (float*)d_out + (size_t)n * DD;
        } else {
            int b = it & 1;
            Pd = gP + (size_t)b * NMAX * DD;
            Md = gM + (size_t)b * NMAX * DD;
        }
        diffuse_k<<<grid, 256>>>((const float4*)Ps, (const float4*)Ms,
                                 (const float4*)X, (float4*)Pd, (float4*)Md, n, E);
        Ps = Pd;
        Ms = Md;
    }
}

// round 3
// speedup vs baseline: 1.0843x; 1.0843x over previous
#include <cuda_runtime.h>

// SidNetLayer: N=50000 nodes, E=600000 edges per signed adjacency, D=128,
// K=10 diffusion layers, restart C=0.15.
//
//   new_P = Ap*P + Am*M + 0.15*X
//   new_M = Am*P + Ap*M
//
// Merged signed CSR: one edge list per output row containing both positive
// and negative edges, sign flag in bit 31 of col. One warp per row,
// accumulators in registers, warp-coalesced float4 gathers, per-edge
// base-pointer select for the P<->M routing.

#define NMAX  50000
#define EMAX  600000
#define DD    128
#define DV    32          // D/4 float4 per row
#define KITER 10
#define CREST 0.15f

// ---------------- persistent device scratch --------------------------------
__device__ int   g_cnt[NMAX];                 // per-row combined edge count
__device__ int   g_start[NMAX];               // exclusive row starts
__device__ int   g_cur[NMAX];                 // scatter cursors (init = start)
__device__ int   g_col[2 * EMAX];             // merged cols (bit31 = negative flag)
__device__ float g_val[2 * EMAX];             // merged vals
// ping-pong: each buffer holds P rows [0,N) then M rows [N,2N), adjacent.
__device__ float g_PM[2][(size_t)2 * NMAX * DD];

// ---------------- CSR build -------------------------------------------------
__global__ void zero_k(int n) {
    int i = blockIdx.x * blockDim.x + threadIdx.x;
    if (i < n) g_cnt[i] = 0;
}

__global__ void hist_k(const int* __restrict__ rp, const int* __restrict__ rm, int E) {
    int i = blockIdx.x * blockDim.x + threadIdx.x;
    if (i < E) {
        atomicAdd(&g_cnt[rp[i]], 1);
        atomicAdd(&g_cnt[rm[i]], 1);
    }
}

// Single-kernel exclusive scan of g_cnt[0..n) -> g_start (and g_cur).
// Block b computes its cross-block prefix by brute-force summing
// g_cnt[0..b*1024) (~5MB total reads across all blocks, negligible).
__global__ void __launch_bounds__(1024)
scan_k(int n) {
    __shared__ int warp_inc[32];
    __shared__ int warp_off[32];
    __shared__ int red[32];
    __shared__ int sprefix;

    int tid  = threadIdx.x;
    int lane = tid & 31;
    int wid  = tid >> 5;
    int gid  = blockIdx.x * 1024 + tid;

    int v = (gid < n) ? g_cnt[gid] : 0;

    int x = v;
#pragma unroll
    for (int o = 1; o < 32; o <<= 1) {
        int y = __shfl_up_sync(0xffffffffu, x, o);
        if (lane >= o) x += y;
    }
    if (lane == 31) warp_inc[wid] = x;

    int ps = 0;
    int lim = blockIdx.x * 1024;
    for (int i = tid; i < lim; i += 1024) ps += g_cnt[i];
#pragma unroll
    for (int o = 16; o > 0; o >>= 1) ps += __shfl_down_sync(0xffffffffu, ps, o);
    if (lane == 0) red[wid] = ps;
    __syncthreads();

    if (tid < 32) {
        int s = warp_inc[tid];
        int t = s;
#pragma unroll
        for (int o = 1; o < 32; o <<= 1) {
            int y = __shfl_up_sync(0xffffffffu, t, o);
            if (tid >= o) t += y;
        }
        warp_off[tid] = t - s;
        int r = red[tid];
#pragma unroll
        for (int o = 16; o > 0; o >>= 1) r += __shfl_down_sync(0xffffffffu, r, o);
        if (tid == 0) sprefix = r;
    }
    __syncthreads();

    if (gid < n) {
        int st = sprefix + warp_off[wid] + (x - v);
        g_start[gid] = st;
        g_cur[gid]   = st;
    }
}

__global__ void scatter_k(const int* __restrict__ rp, const int* __restrict__ cp,
                          const float* __restrict__ vp,
                          const int* __restrict__ rm, const int* __restrict__ cm,
                          const float* __restrict__ vm, int E) {
    int i = blockIdx.x * blockDim.x + threadIdx.x;
    if (i >= E) return;
    int pos = atomicAdd(&g_cur[rp[i]], 1);
    g_col[pos] = cp[i];
    g_val[pos] = vp[i];
    pos = atomicAdd(&g_cur[rm[i]], 1);
    g_col[pos] = cm[i] | 0x80000000;
    g_val[pos] = vm[i];
}

// ---------------- fused diffusion iteration ---------------------------------
// One warp per row. flag ? (accP += v*M[c], accM += v*P[c])
//                        : (accP += v*P[c], accM += v*M[c])
__global__ void __launch_bounds__(256)
diffuse_k(const float4* __restrict__ Ps, const float4* __restrict__ Ms,
          const float4* __restrict__ X4,
          float4* __restrict__ Pd, float4* __restrict__ Md,
          int n, int Etot) {
    int w = (blockIdx.x * blockDim.x + threadIdx.x) >> 5;
    int lane = threadIdx.x & 31;
    if (w >= n) return;

    float4 x = __ldg(&X4[(size_t)w * DV + lane]);
    float aP0 = CREST * x.x, aP1 = CREST * x.y, aP2 = CREST * x.z, aP3 = CREST * x.w;
    float aM0 = 0.f, aM1 = 0.f, aM2 = 0.f, aM3 = 0.f;

    int s = g_start[w];
    int e = (w + 1 < n) ? g_start[w + 1] : Etot;

    for (int base = s; base < e; base += 32) {
        int idx = base + lane;
        int cw = 0; float vw = 0.f;
        if (idx < e) { cw = g_col[idx]; vw = g_val[idx]; }
        int cnt = min(32, e - base);
#pragma unroll 4
        for (int j = 0; j < cnt; j++) {
            int   cj = __shfl_sync(0xffffffffu, cw, j);
            float vj = __shfl_sync(0xffffffffu, vw, j);
            size_t off = (size_t)(cj & 0x7fffffff) * DV + lane;
            const float4* A = (cj < 0) ? Ms : Ps;   // feeds accP
            const float4* B = (cj < 0) ? Ps : Ms;   // feeds accM
            float4 a = __ldg(&A[off]);
            float4 b = __ldg(&B[off]);
            aP0 += vj * a.x; aP1 += vj * a.y; aP2 += vj * a.z; aP3 += vj * a.w;
            aM0 += vj * b.x; aM1 += vj * b.y; aM2 += vj * b.z; aM3 += vj * b.w;
        }
    }

    Pd[(size_t)w * DV + lane] = make_float4(aP0, aP1, aP2, aP3);
    Md[(size_t)w * DV + lane] = make_float4(aM0, aM1, aM2, aM3);
}

// ---------------- launch -----------------------------------------------------
extern "C" void kernel_launch(void* const* d_in, const int* in_sizes, int n_in,
                              void* d_out, int out_size) {
    const int*   rp = (const int*)d_in[0];
    const int*   cp = (const int*)d_in[1];
    const float* vp = (const float*)d_in[2];
    const int*   rm = (const int*)d_in[3];
    const int*   cm = (const int*)d_in[4];
    const float* vm = (const float*)d_in[5];
    const float* X  = (const float*)d_in[6];
    const float* M0 = (const float*)d_in[7];

    int E = in_sizes[0];
    int n = in_sizes[6] / DD;
    int Etot = 2 * E;

    // CSR build: 4 launches (indices 0-3) so ncu -s 5 lands on diffuse iter #2.
    zero_k<<<(n + 255) / 256, 256>>>(n);
    hist_k<<<(E + 255) / 256, 256>>>(rp, rm, E);
    scan_k<<<(n + 1023) / 1024, 1024>>>(n);
    scatter_k<<<(E + 255) / 256, 256>>>(rp, cp, vp, rm, cm, vm, E);

    float* gPM = nullptr;
    cudaGetSymbolAddress((void**)&gPM, g_PM);

    const float* Ps = X;
    const float* Ms = M0;
    int grid = (n + 7) / 8;   // 8 warps / 256-thread block, 1 warp per row

    for (int it = 0; it < KITER; ++it) {
        float *Pd, *Md;
        if (it == KITER - 1) {
            Pd = (float*)d_out;
            Md = (float*)d_out + (size_t)n * DD;
        } else {
            int b = it & 1;
            float* basep = gPM + (size_t)b * 2 * NMAX * DD;
            Pd = basep;                         // P and M adjacent in one buffer
            Md = basep + (size_t)n * DD;
        }
        diffuse_k<<<grid, 256>>>((const float4*)Ps, (const float4*)Ms,
                                 (const float4*)X, (float4*)Pd, (float4*)Md,
                                 n, Etot);
        Ps = Pd;
        Ms = Md;
    }
}

// round 6
// speedup vs baseline: 1.0992x; 1.0137x over previous
#include <cuda_runtime.h>

// SidNetLayer: N=50000, E=600000 per signed adjacency, D=128, K=10, C=0.15.
//   new_P = Ap*P + Am*M + 0.15*X
//   new_M = Am*P + Ap*M
// Merged signed CSR (sign in bit31 of col), packed {col,val} int2 records.
// One warp per output row, register accumulators, warp-coalesced float4
// gathers, per-edge base-pointer select for P<->M routing.

#define NMAX  50000
#define EMAX  600000
#define DD    128
#define DV    32          // D/4 float4 per row
#define KITER 10
#define CREST 0.15f

// ---------------- persistent device scratch --------------------------------
__device__ int  g_cnt[NMAX];      // per-row combined edge count (zero at entry;
                                  // scatter_k restores the invariant each call)
__device__ int  g_start[NMAX];    // exclusive row starts
__device__ int  g_cur[NMAX];      // scatter cursors (init = start)
__device__ int2 g_cv[2 * EMAX];   // packed {col | bit31 sign, val bits}
__device__ float g_PM[2][(size_t)2 * NMAX * DD];  // ping-pong, P then M

// ---------------- CSR build (3 launches) ------------------------------------
__global__ void hist_k(const int* __restrict__ rp, const int* __restrict__ rm, int E) {
    int i = blockIdx.x * blockDim.x + threadIdx.x;
    if (i < E) {
        atomicAdd(&g_cnt[rp[i]], 1);
        atomicAdd(&g_cnt[rm[i]], 1);
    }
}

// Exclusive scan of g_cnt[0..n) -> g_start and g_cur. Cross-block prefix via
// brute-force re-sum of preceding counts (~5MB total, negligible).
__global__ void __launch_bounds__(1024)
scan_k(int n) {
    __shared__ int warp_inc[32];
    __shared__ int warp_off[32];
    __shared__ int red[32];
    __shared__ int sprefix;

    int tid  = threadIdx.x;
    int lane = tid & 31;
    int wid  = tid >> 5;
    int gid  = blockIdx.x * 1024 + tid;

    int v = (gid < n) ? g_cnt[gid] : 0;

    int x = v;
#pragma unroll
    for (int o = 1; o < 32; o <<= 1) {
        int y = __shfl_up_sync(0xffffffffu, x, o);
        if (lane >= o) x += y;
    }
    if (lane == 31) warp_inc[wid] = x;

    int ps = 0;
    int lim = blockIdx.x * 1024;
    for (int i = tid; i < lim; i += 1024) ps += g_cnt[i];
#pragma unroll
    for (int o = 16; o > 0; o >>= 1) ps += __shfl_down_sync(0xffffffffu, ps, o);
    if (lane == 0) red[wid] = ps;
    __syncthreads();

    if (tid < 32) {
        int s = warp_inc[tid];
        int t = s;
#pragma unroll
        for (int o = 1; o < 32; o <<= 1) {
            int y = __shfl_up_sync(0xffffffffu, t, o);
            if (tid >= o) t += y;
        }
        warp_off[tid] = t - s;
        int r = red[tid];
#pragma unroll
        for (int o = 16; o > 0; o >>= 1) r += __shfl_down_sync(0xffffffffu, r, o);
        if (tid == 0) sprefix = r;
    }
    __syncthreads();

    if (gid < n) {
        int st = sprefix + warp_off[wid] + (x - v);
        g_start[gid] = st;
        g_cur[gid]   = st;
    }
}

__global__ void scatter_k(const int* __restrict__ rp, const int* __restrict__ cp,
                          const float* __restrict__ vp,
                          const int* __restrict__ rm, const int* __restrict__ cm,
                          const float* __restrict__ vm, int E, int n) {
    int i = blockIdx.x * blockDim.x + threadIdx.x;
    // restore g_cnt = 0 invariant for the next call (scan_k has consumed it;
    // nothing reads g_cnt after this point in the current call)
    if (i < n) g_cnt[i] = 0;
    if (i >= E) return;
    int pos = atomicAdd(&g_cur[rp[i]], 1);
    g_cv[pos] = make_int2(cp[i], __float_as_int(vp[i]));
    pos = atomicAdd(&g_cur[rm[i]], 1);
    g_cv[pos] = make_int2(cm[i] | 0x80000000, __float_as_int(vm[i]));
}

// ---------------- fused diffusion iteration ---------------------------------
// One warp per row. flag ? (accP += v*M[c], accM += v*P[c])
//                        : (accP += v*P[c], accM += v*M[c])
__global__ void __launch_bounds__(256)
diffuse_k(const float4* __restrict__ Ps, const float4* __restrict__ Ms,
          const float4* __restrict__ X4,
          float4* __restrict__ Pd, float4* __restrict__ Md,
          int n, int Etot) {
    int w = (blockIdx.x * blockDim.x + threadIdx.x) >> 5;
    int lane = threadIdx.x & 31;
    if (w >= n) return;

    float4 x = __ldg(&X4[(size_t)w * DV + lane]);
    float aP0 = CREST * x.x, aP1 = CREST * x.y, aP2 = CREST * x.z, aP3 = CREST * x.w;
    float aM0 = 0.f, aM1 = 0.f, aM2 = 0.f, aM3 = 0.f;

    int s = g_start[w];
    int e = (w + 1 < n) ? g_start[w + 1] : Etot;

    for (int base = s; base < e; base += 32) {
        int idx = base + lane;
        int cw = 0; float vw = 0.f;
        if (idx < e) {
            int2 cv = g_cv[idx];
            cw = cv.x;
            vw = __int_as_float(cv.y);
        }
        int cnt = min(32, e - base);
#pragma unroll 4
        for (int j = 0; j < cnt; j++) {
            int   cj = __shfl_sync(0xffffffffu, cw, j);
            float vj = __shfl_sync(0xffffffffu, vw, j);
            size_t off = (size_t)(cj & 0x7fffffff) * DV + lane;
            const float4* A = (cj < 0) ? Ms : Ps;   // feeds accP
            const float4* B = (cj < 0) ? Ps : Ms;   // feeds accM
            float4 a = __ldg(&A[off]);
            float4 b = __ldg(&B[off]);
            aP0 += vj * a.x; aP1 += vj * a.y; aP2 += vj * a.z; aP3 += vj * a.w;
            aM0 += vj * b.x; aM1 += vj * b.y; aM2 += vj * b.z; aM3 += vj * b.w;
        }
    }

    Pd[(size_t)w * DV + lane] = make_float4(aP0, aP1, aP2, aP3);
    Md[(size_t)w * DV + lane] = make_float4(aM0, aM1, aM2, aM3);
}

// ---------------- launch -----------------------------------------------------
extern "C" void kernel_launch(void* const* d_in, const int* in_sizes, int n_in,
                              void* d_out, int out_size) {
    const int*   rp = (const int*)d_in[0];
    const int*   cp = (const int*)d_in[1];
    const float* vp = (const float*)d_in[2];
    const int*   rm = (const int*)d_in[3];
    const int*   cm = (const int*)d_in[4];
    const float* vm = (const float*)d_in[5];
    const float* X  = (const float*)d_in[6];
    const float* M0 = (const float*)d_in[7];

    int E = in_sizes[0];
    int n = in_sizes[6] / DD;
    int Etot = 2 * E;

    // CSR build: 3 launches, so the ncu skip window lands on a diffuse iter.
    hist_k<<<(E + 255) / 256, 256>>>(rp, rm, E);
    scan_k<<<(n + 1023) / 1024, 1024>>>(n);
    scatter_k<<<(E + 255) / 256, 256>>>(rp, cp, vp, rm, cm, vm, E, n);

    float* gPM = nullptr;
    cudaGetSymbolAddress((void**)&gPM, g_PM);

    const float* Ps = X;
    const float* Ms = M0;
    int grid = (n + 7) / 8;   // 8 warps / 256-thread block, 1 warp per row

    for (int it = 0; it < KITER; ++it) {
        float *Pd, *Md;
        if (it == KITER - 1) {
            Pd = (float*)d_out;
            Md = (float*)d_out + (size_t)n * DD;
        } else {
            int b = it & 1;
            float* basep = gPM + (size_t)b * 2 * NMAX * DD;
            Pd = basep;
            Md = basep + (size_t)n * DD;
        }
        diffuse_k<<<grid, 256>>>((const float4*)Ps, (const float4*)Ms,
                                 (const float4*)X, (float4*)Pd, (float4*)Md,
                                 n, Etot);
        Ps = Pd;
        Ms = Md;
    }
}

// round 7
// speedup vs baseline: 1.1891x; 1.0818x over previous
#include <cuda_runtime.h>

// SidNetLayer: N=50000, E=600000 per signed adjacency, D=128, K=10, C=0.15.
//   new_P = Ap*P + Am*M + 0.15*X
//   new_M = Am*P + Ap*M
// Merged signed CSR (sign in bit31 of col), packed {col,val} int2 records.
// One warp per output row. Edge records are read by ALL lanes at the same
// address (broadcast LDG.64, 1 wavefront, L1-resident: 16 edges per line) —
// no shuffles, no staging. Dense gathers are warp-coalesced float4.

#define NMAX  50000
#define EMAX  600000
#define DD    128
#define DV    32          // D/4 float4 per row
#define KITER 10
#define CREST 0.15f

// ---------------- persistent device scratch --------------------------------
__device__ int  g_cnt[NMAX];      // zero at entry; scatter_k restores invariant
__device__ int  g_start[NMAX];    // exclusive row starts
__device__ int  g_cur[NMAX];      // scatter cursors (init = start)
__device__ int2 g_cv[2 * EMAX];   // packed {col | bit31 sign, val bits}
__device__ float g_PM[2][(size_t)2 * NMAX * DD];  // ping-pong, P then M

// ---------------- CSR build (3 launches) ------------------------------------
__global__ void hist_k(const int* __restrict__ rp, const int* __restrict__ rm, int E) {
    int i = blockIdx.x * blockDim.x + threadIdx.x;
    if (i < E) {
        atomicAdd(&g_cnt[rp[i]], 1);
        atomicAdd(&g_cnt[rm[i]], 1);
    }
}

__global__ void __launch_bounds__(1024)
scan_k(int n) {
    __shared__ int warp_inc[32];
    __shared__ int warp_off[32];
    __shared__ int red[32];
    __shared__ int sprefix;

    int tid  = threadIdx.x;
    int lane = tid & 31;
    int wid  = tid >> 5;
    int gid  = blockIdx.x * 1024 + tid;

    int v = (gid < n) ? g_cnt[gid] : 0;

    int x = v;
#pragma unroll
    for (int o = 1; o < 32; o <<= 1) {
        int y = __shfl_up_sync(0xffffffffu, x, o);
        if (lane >= o) x += y;
    }
    if (lane == 31) warp_inc[wid] = x;

    int ps = 0;
    int lim = blockIdx.x * 1024;
    for (int i = tid; i < lim; i += 1024) ps += g_cnt[i];
#pragma unroll
    for (int o = 16; o > 0; o >>= 1) ps += __shfl_down_sync(0xffffffffu, ps, o);
    if (lane == 0) red[wid] = ps;
    __syncthreads();

    if (tid < 32) {
        int s = warp_inc[tid];
        int t = s;
#pragma unroll
        for (int o = 1; o < 32; o <<= 1) {
            int y = __shfl_up_sync(0xffffffffu, t, o);
            if (tid >= o) t += y;
        }
        warp_off[tid] = t - s;
        int r = red[tid];
#pragma unroll
        for (int o = 16; o > 0; o >>= 1) r += __shfl_down_sync(0xffffffffu, r, o);
        if (tid == 0) sprefix = r;
    }
    __syncthreads();

    if (gid < n) {
        int st = sprefix + warp_off[wid] + (x - v);
        g_start[gid] = st;
        g_cur[gid]   = st;
    }
}

__global__ void scatter_k(const int* __restrict__ rp, const int* __restrict__ cp,
                          const float* __restrict__ vp,
                          const int* __restrict__ rm, const int* __restrict__ cm,
                          const float* __restrict__ vm, int E, int n) {
    int i = blockIdx.x * blockDim.x + threadIdx.x;
    if (i < n) g_cnt[i] = 0;   // restore invariant for next call
    if (i >= E) return;
    int pos = atomicAdd(&g_cur[rp[i]], 1);
    g_cv[pos] = make_int2(cp[i], __float_as_int(vp[i]));
    pos = atomicAdd(&g_cur[rm[i]], 1);
    g_cv[pos] = make_int2(cm[i] | 0x80000000, __float_as_int(vm[i]));
}

// ---------------- fused diffusion iteration ---------------------------------
// One warp per row. flag ? (accP += v*M[c], accM += v*P[c])
//                        : (accP += v*P[c], accM += v*M[c])
__global__ void __launch_bounds__(128)
diffuse_k(const float4* __restrict__ Ps, const float4* __restrict__ Ms,
          const float4* __restrict__ X4,
          float4* __restrict__ Pd, float4* __restrict__ Md,
          int n, int Etot) {
    int w = (blockIdx.x * blockDim.x + threadIdx.x) >> 5;
    unsigned lane = threadIdx.x & 31;
    if (w >= n) return;

    float4 x = __ldg(&X4[(unsigned)w * DV + lane]);
    float aP0 = CREST * x.x, aP1 = CREST * x.y, aP2 = CREST * x.z, aP3 = CREST * x.w;
    float aM0 = 0.f, aM1 = 0.f, aM2 = 0.f, aM3 = 0.f;

    int s = g_start[w];
    int e = (w + 1 < n) ? g_start[w + 1] : Etot;

#pragma unroll 4
    for (int j = s; j < e; j++) {
        // all lanes load the same 8B record: broadcast, 1 wavefront, L1-hot
        int2 cv = __ldg(&g_cv[j]);
        int   cj = cv.x;
        float vj = __int_as_float(cv.y);
        unsigned off = (unsigned)(cj & 0x7fffffff) * DV + lane;  // 32-bit math
        const float4* A = (cj < 0) ? Ms : Ps;   // feeds accP
        const float4* B = (cj < 0) ? Ps : Ms;   // feeds accM
        float4 a = __ldg(&A[off]);
        float4 b = __ldg(&B[off]);
        aP0 += vj * a.x; aP1 += vj * a.y; aP2 += vj * a.z; aP3 += vj * a.w;
        aM0 += vj * b.x; aM1 += vj * b.y; aM2 += vj * b.z; aM3 += vj * b.w;
    }

    Pd[(unsigned)w * DV + lane] = make_float4(aP0, aP1, aP2, aP3);
    Md[(unsigned)w * DV + lane] = make_float4(aM0, aM1, aM2, aM3);
}

// ---------------- launch -----------------------------------------------------
extern "C" void kernel_launch(void* const* d_in, const int* in_sizes, int n_in,
                              void* d_out, int out_size) {
    const int*   rp = (const int*)d_in[0];
    const int*   cp = (const int*)d_in[1];
    const float* vp = (const float*)d_in[2];
    const int*   rm = (const int*)d_in[3];
    const int*   cm = (const int*)d_in[4];
    const float* vm = (const float*)d_in[5];
    const float* X  = (const float*)d_in[6];
    const float* M0 = (const float*)d_in[7];

    int E = in_sizes[0];
    int n = in_sizes[6] / DD;
    int Etot = 2 * E;

    hist_k<<<(E + 255) / 256, 256>>>(rp, rm, E);
    scan_k<<<(n + 1023) / 1024, 1024>>>(n);
    scatter_k<<<(E + 255) / 256, 256>>>(rp, cp, vp, rm, cm, vm, E, n);

    float* gPM = nullptr;
    cudaGetSymbolAddress((void**)&gPM, g_PM);

    const float* Ps = X;
    const float* Ms = M0;
    int grid = (n + 3) / 4;   // 4 warps / 128-thread block, 1 warp per row

    for (int it = 0; it < KITER; ++it) {
        float *Pd, *Md;
        if (it == KITER - 1) {
            Pd = (float*)d_out;
            Md = (float*)d_out + (size_t)n * DD;
        } else {
            int b = it & 1;
            float* basep = gPM + (size_t)b * 2 * NMAX * DD;
            Pd = basep;
            Md = basep + (size_t)n * DD;
        }
        diffuse_k<<<grid, 128>>>((const float4*)Ps, (const float4*)Ms,
                                 (const float4*)X, (float4*)Pd, (float4*)Md,
                                 n, Etot);
        Ps = Pd;
        Ms = Md;
    }
}